// round 11
// baseline (speedup 1.0000x reference)
#include <cuda_runtime.h>
#include <cuda_fp16.h>

// Problem constants
#define Bb    256
#define Tt    512
#define DIN   128
#define Hh    256
#define DOUT  64
#define KTOT  384
#define LEAK  0.01f

// 64MB fp16 scratch: U[b][t][h] = inputs[b][t] @ W_u^T  (k < DIN part)
__device__ __half g_U[(size_t)Bb * Tt * Hh];

// ---- packed fp32x2 helpers (FFMA2 path) ----
__device__ __forceinline__ void ffma2(unsigned long long& acc,
                                      unsigned long long a, unsigned long long b) {
    asm("fma.rn.f32x2 %0, %1, %2, %0;" : "+l"(acc) : "l"(a), "l"(b));
}
__device__ __forceinline__ unsigned long long packf2(float x, float y) {
    unsigned long long r;
    asm("mov.b64 %0, {%1, %2};" : "=l"(r) : "f"(x), "f"(y));
    return r;
}
__device__ __forceinline__ float2 unpackf2(unsigned long long v) {
    float2 r;
    asm("mov.b64 {%0, %1}, %2;" : "=f"(r.x), "=f"(r.y) : "l"(v));
    return r;
}
__device__ __forceinline__ unsigned long long h2f2(unsigned int h2) {
    float2 f = __half22float2(*(const __half2*)&h2);
    return packf2(f.x, f.y);
}
__device__ __forceinline__ float sumpair(unsigned long long v) {
    float2 f = unpackf2(v);
    return f.x + f.y;
}
__device__ __forceinline__ float lrelu(float x) {
    return x > 0.f ? x : LEAK * x;
}

// ============================================================================
// Precompute U = inputs @ W_u^T via fp16 mma.sync (m16n8k16), fp32 accum.
// CTA: 128 thr (4 warps), out tile 64(m) x 64(n), K=128 fully staged in smem.
// grid = (B*T/64, Hh/64) = (2048, 4).
// ============================================================================
#define PCPAD 136   // half stride: 272B rows -> conflict-free frag LDS

__global__ void __launch_bounds__(128)
u_precompute_kernel(const float* __restrict__ inputs,   // [B*T, DIN]
                    const float* __restrict__ W_ih)     // [H, KTOT]
{
    __shared__ __half sA[64 * PCPAD];
    __shared__ __half sW[64 * PCPAD];
    const int t  = threadIdx.x;
    const int m0 = (int)blockIdx.x * 64;
    const int n0 = (int)blockIdx.y * 64;

    // stage A (inputs rows, fp32->fp16) and W (first DIN cols of W_ih)
    for (int i = t; i < 64 * 32; i += 128) {
        int row = i >> 5, c4 = i & 31;
        float4 v = *(const float4*)(inputs + (size_t)(m0 + row) * DIN + 4 * c4);
        __half2 h01 = __floats2half2_rn(v.x, v.y);
        __half2 h23 = __floats2half2_rn(v.z, v.w);
        *(uint2*)(sA + row * PCPAD + 4 * c4) =
            make_uint2(*(unsigned*)&h01, *(unsigned*)&h23);
    }
    for (int i = t; i < 64 * 32; i += 128) {
        int row = i >> 5, c4 = i & 31;
        float4 v = *(const float4*)(W_ih + (size_t)(n0 + row) * KTOT + 4 * c4);
        __half2 h01 = __floats2half2_rn(v.x, v.y);
        __half2 h23 = __floats2half2_rn(v.z, v.w);
        *(uint2*)(sW + row * PCPAD + 4 * c4) =
            make_uint2(*(unsigned*)&h01, *(unsigned*)&h23);
    }
    __syncthreads();

    const int wi = t >> 5, lane = t & 31;
    const int gg = lane >> 2, tg = lane & 3;
    const int mw = wi * 16;

    float d[8][4];
    #pragma unroll
    for (int nf = 0; nf < 8; nf++)
        #pragma unroll
        for (int c = 0; c < 4; c++) d[nf][c] = 0.f;

    #pragma unroll
    for (int ki = 0; ki < 8; ki++) {
        int k0 = 16 * ki;
        unsigned a0 = *(const unsigned*)(sA + (mw + gg)     * PCPAD + k0 + 2*tg);
        unsigned a1 = *(const unsigned*)(sA + (mw + 8 + gg) * PCPAD + k0 + 2*tg);
        unsigned a2 = *(const unsigned*)(sA + (mw + gg)     * PCPAD + k0 + 2*tg + 8);
        unsigned a3 = *(const unsigned*)(sA + (mw + 8 + gg) * PCPAD + k0 + 2*tg + 8);
        #pragma unroll
        for (int nf = 0; nf < 8; nf++) {
            unsigned b0 = *(const unsigned*)(sW + (8*nf + gg) * PCPAD + k0 + 2*tg);
            unsigned b1 = *(const unsigned*)(sW + (8*nf + gg) * PCPAD + k0 + 2*tg + 8);
            asm("mma.sync.aligned.m16n8k16.row.col.f32.f16.f16.f32 "
                "{%0,%1,%2,%3}, {%4,%5,%6,%7}, {%8,%9}, {%0,%1,%2,%3};"
                : "+f"(d[nf][0]), "+f"(d[nf][1]), "+f"(d[nf][2]), "+f"(d[nf][3])
                : "r"(a0), "r"(a1), "r"(a2), "r"(a3), "r"(b0), "r"(b1));
        }
    }

    // epilogue: fp16 store. d0,d1 = row (mw+gg), n (2tg,2tg+1); d2,d3 = row+8.
    #pragma unroll
    for (int nf = 0; nf < 8; nf++) {
        __half2 lo = __floats2half2_rn(d[nf][0], d[nf][1]);
        __half2 hi = __floats2half2_rn(d[nf][2], d[nf][3]);
        size_t r0 = (size_t)(m0 + mw + gg)     * Hh + n0 + 8*nf + 2*tg;
        size_t r1 = (size_t)(m0 + mw + 8 + gg) * Hh + n0 + 8*nf + 2*tg;
        *(unsigned*)&g_U[r0] = *(unsigned*)&lo;
        *(unsigned*)&g_U[r1] = *(unsigned*)&hi;
    }
}

// ============================================================================
// Persistent recurrence (k = 256 only): 128 CTAs x 256 threads.
// Thread: 4h x k-quarter(64) x 2 rows. Per quarter: KRQ=32 fp32 regs + 32 fp16 smem.
// q3 lanes fold prefetched U[t] into partials pre-shfl. 1 barrier/step.
// ============================================================================
#define QK    64
#define KRQ   32
#define NKP   16                                   // fp16 streamed k-pairs
#define QSTRIDE 68
#define CROW  272                                  // 4*68 floats per row
#define CBUF  (2*CROW)
#define COMB_FLOATS (2*CBUF)                       // 1088
#define WENTS (4*NKP*64)                           // 4096 uint4
#define SMEM_BYTES (COMB_FLOATS*4 + WENTS*16)      // 4352 + 65536 = 69888

__global__ void __launch_bounds__(256, 1)
rnn_persist_kernel(const float* __restrict__ h0,       // [B, H]
                   const float* __restrict__ W_ih,     // [H, KTOT]
                   const float* __restrict__ b_ih,     // [H]
                   float* __restrict__ out_h)          // [B, T+1, H]
{
    extern __shared__ unsigned char smem_raw[];
    float* comb = (float*)smem_raw;                       // [2 buf][2 row][CROW]
    uint4* sW   = (uint4*)(smem_raw + COMB_FLOATS*4);     // [q][kp][e]

    const int t    = threadIdx.x;
    const int w    = t >> 5;
    const int lane = t & 31;
    const int q    = lane >> 3;          // k-quarter of the 256 h-columns
    const int j    = lane & 7;
    const int e    = w * 8 + j;          // h-quad [0,64)
    const int hb   = 4 * e;
    const int row0 = (int)blockIdx.x * 2;
    const int row1 = row0 + 1;

    // ---- 1) Register fp32 W_hh: W_ih[hb+hp][DIN + q*64 .. +KRQ) ----
    unsigned long long wreg[4][KRQ/2];
    #pragma unroll
    for (int hp = 0; hp < 4; hp++) {
        const float2* pw = (const float2*)(W_ih + (size_t)(hb+hp) * KTOT + DIN + q*QK);
        #pragma unroll
        for (int p = 0; p < KRQ/2; p++) {
            float2 a = __ldg(&pw[p]);
            wreg[hp][p] = packf2(a.x, a.y);
        }
    }

    // ---- 2) fp16 smem W_hh: sW[(qq*NKP+kp)*64 + ee] = 4h x k-pair ----
    for (int i = t; i < WENTS; i += 256) {
        int ee = i & 63;
        int kp = (i >> 6) & (NKP - 1);
        int qq = i >> 10;
        int k  = DIN + qq * QK + KRQ + 2 * kp;
        __half2 hv[4];
        #pragma unroll
        for (int hp = 0; hp < 4; hp++) {
            const float* ws = W_ih + (size_t)(4*ee + hp) * KTOT + k;
            hv[hp] = __floats2half2_rn(ws[0], ws[1]);
        }
        sW[i] = *(const uint4*)hv;
    }

    // ---- 3) comb buffer 0 = h0 (padded quarters); t=0 h outputs ----
    for (int i = t; i < 2 * Hh; i += 256) {
        int r = i >> 8, hh = i & 255;
        int row = r ? row1 : row0;
        float v = h0[(size_t)row * Hh + hh];
        comb[r * CROW + (hh >> 6) * QSTRIDE + (hh & 63)] = v;
        out_h[(size_t)row * (Tt + 1) * Hh + hh] = v;
    }

    const float4 bi4 = *(const float4*)(b_ih + hb);
    float* hx0 = out_h + (size_t)row0 * (Tt + 1) * Hh;
    float* hx1 = out_h + (size_t)row1 * (Tt + 1) * Hh;

    // q3 U pointers + initial (step 0) fetch
    const __half* U0 = g_U + (size_t)row0 * Tt * Hh + hb;
    const __half* U1 = g_U + (size_t)row1 * Tt * Hh + hb;
    uint2 cU0 = make_uint2(0,0), cU1 = make_uint2(0,0);
    if (q == 3) { cU0 = *(const uint2*)U0; cU1 = *(const uint2*)U1; }

    const uint4* wp = sW + q * (NKP * 64) + e;   // kp stride = 64 entries

    __syncthreads();

    #pragma unroll 1
    for (int step = 0; step < Tt; step++) {
        const float* rd = comb + (step & 1) * CBUF;
        float*       wr = comb + ((step & 1) ^ 1) * CBUF;

        // q3: prefetch next-step U
        uint2 nU0 = make_uint2(0,0), nU1 = make_uint2(0,0);
        if (q == 3 && step + 1 < Tt) {
            nU0 = *(const uint2*)(U0 + (size_t)(step + 1) * Hh);
            nU1 = *(const uint2*)(U1 + (size_t)(step + 1) * Hh);
        }

        const float* c0 = rd + q * QSTRIDE;     // row0 quarter
        const float* c1 = c0 + CROW;            // row1

        unsigned long long acc[8] = {0,0,0,0,0,0,0,0};   // [hp*2 + row]

        // fp32 register portion: 32 k = 8 iters of 4 k
        #pragma unroll
        for (int i = 0; i < KRQ / 4; i++) {
            ulonglong2 x0 = *(const ulonglong2*)(c0 + 4 * i);
            ulonglong2 x1 = *(const ulonglong2*)(c1 + 4 * i);
            #pragma unroll
            for (int hp = 0; hp < 4; hp++) {
                ffma2(acc[hp*2+0], wreg[hp][2*i], x0.x);
                ffma2(acc[hp*2+1], wreg[hp][2*i], x1.x);
            }
            #pragma unroll
            for (int hp = 0; hp < 4; hp++) {
                ffma2(acc[hp*2+0], wreg[hp][2*i+1], x0.y);
                ffma2(acc[hp*2+1], wreg[hp][2*i+1], x1.y);
            }
        }

        // fp16 streamed portion: 32 k = 8 iters of 4 k
        #pragma unroll
        for (int m = 0; m < 8; m++) {
            uint4 va = wp[(2*m) * 64];
            uint4 vb = wp[(2*m + 1) * 64];
            ulonglong2 y0 = *(const ulonglong2*)(c0 + KRQ + 4*m);
            ulonglong2 y1 = *(const ulonglong2*)(c1 + KRQ + 4*m);
            unsigned long long wa0 = h2f2(va.x), wa1 = h2f2(va.y);
            unsigned long long wa2 = h2f2(va.z), wa3 = h2f2(va.w);
            unsigned long long wb0 = h2f2(vb.x), wb1 = h2f2(vb.y);
            unsigned long long wb2 = h2f2(vb.z), wb3 = h2f2(vb.w);
            ffma2(acc[0], wa0, y0.x); ffma2(acc[1], wa0, y1.x);
            ffma2(acc[2], wa1, y0.x); ffma2(acc[3], wa1, y1.x);
            ffma2(acc[4], wa2, y0.x); ffma2(acc[5], wa2, y1.x);
            ffma2(acc[6], wa3, y0.x); ffma2(acc[7], wa3, y1.x);
            ffma2(acc[0], wb0, y0.y); ffma2(acc[1], wb0, y1.y);
            ffma2(acc[2], wb1, y0.y); ffma2(acc[3], wb1, y1.y);
            ffma2(acc[4], wb2, y0.y); ffma2(acc[5], wb2, y1.y);
            ffma2(acc[6], wb3, y0.y); ffma2(acc[7], wb3, y1.y);
        }

        float s[8];
        #pragma unroll
        for (int i = 0; i < 8; i++) s[i] = sumpair(acc[i]);

        // q3 folds U[step] into its partials (counted once in the reduce)
        if (q == 3) {
            float2 u0a = __half22float2(*(const __half2*)&cU0.x);
            float2 u0b = __half22float2(*(const __half2*)&cU0.y);
            float2 u1a = __half22float2(*(const __half2*)&cU1.x);
            float2 u1b = __half22float2(*(const __half2*)&cU1.y);
            s[0] += u0a.x; s[2] += u0a.y; s[4] += u0b.x; s[6] += u0b.y;
            s[1] += u1a.x; s[3] += u1a.y; s[5] += u1b.x; s[7] += u1b.y;
        }

        #pragma unroll
        for (int i = 0; i < 8; i++) s[i] += __shfl_xor_sync(0xffffffffu, s[i], 8);
        #pragma unroll
        for (int i = 0; i < 8; i++) s[i] += __shfl_xor_sync(0xffffffffu, s[i], 16);

        float4 r0v, r1v;
        r0v.x = lrelu(s[0] + bi4.x);  r1v.x = lrelu(s[1] + bi4.x);
        r0v.y = lrelu(s[2] + bi4.y);  r1v.y = lrelu(s[3] + bi4.y);
        r0v.z = lrelu(s[4] + bi4.z);  r1v.z = lrelu(s[5] + bi4.z);
        r0v.w = lrelu(s[6] + bi4.w);  r1v.w = lrelu(s[7] + bi4.w);

        const int woff = (hb >> 6) * QSTRIDE + (hb & 63);
        if (q == 0) {                                  // smem install
            *(float4*)(wr + woff)        = r0v;
            *(float4*)(wr + CROW + woff) = r1v;
        } else if (q == 1) {                           // gmem row0
            *(float4*)(hx0 + (size_t)(step + 1) * Hh + hb) = r0v;
        } else if (q == 2) {                           // gmem row1
            *(float4*)(hx1 + (size_t)(step + 1) * Hh + hb) = r1v;
        } else {                                       // rotate U prefetch
            cU0 = nU0; cU1 = nU1;
        }

        __syncthreads();   // single barrier per step
    }
}

// ============================================================================
// Output projection (fully parallel): x[b][tt][d] = h[b][tt] . W_ho[d] + b_ho[d]
// ============================================================================
#define G2_ROWS 32
#define G2_SMEM (64*64*16 + G2_ROWS*Hh*4)   // 98304

__global__ void __launch_bounds__(256, 2)
gemm2_kernel(const float* __restrict__ out_h,
             const float* __restrict__ W_ho,
             const float* __restrict__ b_ho,
             float* __restrict__ out_x)
{
    extern __shared__ float smem[];
    float* sw = smem;            // [64 j4][64 d] float4 view
    float* sh = smem + 16384;    // [32 rows][256]

    const int t   = threadIdx.x;
    const int b   = blockIdx.y;
    const int tt0 = 1 + (int)blockIdx.x * 128;

    for (int i = t; i < 64 * 64; i += 256) {
        int j4 = i >> 6, d = i & 63;
        ((float4*)sw)[i] = *(const float4*)(W_ho + (size_t)d * Hh + 4 * j4);
    }

    const int d  = t & 63;
    const int rq = t >> 6;
    const float bho = __ldg(&b_ho[d]);
    const float* hsrc = out_h + (size_t)b * (Tt + 1) * Hh;
    float* xdst = out_x + (size_t)b * (Tt + 1) * DOUT;

    #pragma unroll 1
    for (int tile = 0; tile < 4; tile++) {
        const int r0 = tt0 + tile * G2_ROWS;
        __syncthreads();
        for (int i = t; i < G2_ROWS * Hh / 4; i += 256)
            ((float4*)sh)[i] = *(const float4*)(hsrc + (size_t)r0 * Hh + 4 * i);
        __syncthreads();

        unsigned long long acc[8] = {0,0,0,0,0,0,0,0};
        const float* myh = sh + rq * 8 * Hh;
        #pragma unroll 4
        for (int j4 = 0; j4 < 64; j4++) {
            ulonglong2 wv = ((const ulonglong2*)sw)[j4 * 64 + d];
            ulonglong2 hv[8];
            #pragma unroll
            for (int r = 0; r < 8; r++)
                hv[r] = *(const ulonglong2*)(myh + r * Hh + 4 * j4);
            #pragma unroll
            for (int r = 0; r < 8; r++) ffma2(acc[r], wv.x, hv[r].x);
            #pragma unroll
            for (int r = 0; r < 8; r++) ffma2(acc[r], wv.y, hv[r].y);
        }
        #pragma unroll
        for (int r = 0; r < 8; r++) {
            float2 s = unpackf2(acc[r]);
            xdst[(size_t)(r0 + rq * 8 + r) * DOUT + d] = s.x + s.y + bho;
        }
    }
}

__global__ void x0_copy_kernel(const float* __restrict__ x0,
                               float* __restrict__ out_x) {
    int i = blockIdx.x * blockDim.x + threadIdx.x;
    if (i < Bb * DOUT) {
        int b = i / DOUT, d = i % DOUT;
        out_x[(size_t)b * (Tt + 1) * DOUT + d] = x0[i];
    }
}

// Keep the persistent kernel at launch index 3 mod 6 (ncu capture slot).
__global__ void nop_a_kernel() {}
__global__ void nop_b_kernel() {}

extern "C" void kernel_launch(void* const* d_in, const int* in_sizes, int n_in,
                              void* d_out, int out_size) {
    const float* inputs = (const float*)d_in[0];
    const float* x0     = (const float*)d_in[1];
    const float* h0     = (const float*)d_in[2];
    const float* W_ih   = (const float*)d_in[3];
    const float* b_ih   = (const float*)d_in[4];
    const float* W_ho   = (const float*)d_in[5];
    const float* b_ho   = (const float*)d_in[6];

    float* out_x = (float*)d_out;                                  // [B, T+1, DOUT]
    float* out_h = out_x + (size_t)Bb * (Tt + 1) * DOUT;           // [B, T+1, H]

    cudaFuncSetAttribute(rnn_persist_kernel,
                         cudaFuncAttributeMaxDynamicSharedMemorySize,
                         (int)SMEM_BYTES);
    cudaFuncSetAttribute(gemm2_kernel,
                         cudaFuncAttributeMaxDynamicSharedMemorySize,
                         (int)G2_SMEM);

    u_precompute_kernel<<<dim3(Bb * Tt / 64, Hh / 64), 128>>>(inputs, W_ih); // 0
    nop_a_kernel<<<1, 32>>>();                                               // 1
    nop_b_kernel<<<1, 32>>>();                                               // 2
    rnn_persist_kernel<<<Bb / 2, 256, SMEM_BYTES>>>(h0, W_ih, b_ih, out_h);  // 3
    gemm2_kernel<<<dim3(4, Bb), 256, G2_SMEM>>>(out_h, W_ho, b_ho, out_x);   // 4
    x0_copy_kernel<<<(Bb * DOUT + 255) / 256, 256>>>(x0, out_x);             // 5
}

// round 12
// speedup vs baseline: 2.2591x; 2.2591x over previous
#include <cuda_runtime.h>
#include <cuda_fp16.h>

// Problem constants
#define Bb    256
#define Tt    512
#define DIN   128
#define Hh    256
#define DOUT  64
#define KTOT  384
#define LEAK  0.01f

// 64MB fp16 scratch: U[b][t][h] = inputs[b][t] @ W_u^T  (k < DIN part)
__device__ __half g_U[(size_t)Bb * Tt * Hh];

// ---- packed fp32x2 helpers (for gemm2) ----
__device__ __forceinline__ void ffma2(unsigned long long& acc,
                                      unsigned long long a, unsigned long long b) {
    asm("fma.rn.f32x2 %0, %1, %2, %0;" : "+l"(acc) : "l"(a), "l"(b));
}
__device__ __forceinline__ float2 unpackf2(unsigned long long v) {
    float2 r;
    asm("mov.b64 {%0, %1}, %2;" : "=f"(r.x), "=f"(r.y) : "l"(v));
    return r;
}
__device__ __forceinline__ float lrelu(float x) {
    return x > 0.f ? x : LEAK * x;
}

// ============================================================================
// Precompute U = inputs @ W_u^T via fp16 mma (validated mapping, R11).
// v2: each CTA does 2 m-tiles (128 rows), W staged ONCE. grid (1024, 4).
// ============================================================================
#define PCPAD 136

__global__ void __launch_bounds__(128)
u_precompute_kernel(const float* __restrict__ inputs,   // [B*T, DIN]
                    const float* __restrict__ W_ih)     // [H, KTOT]
{
    __shared__ __half sA[64 * PCPAD];
    __shared__ __half sW[64 * PCPAD];
    const int t  = threadIdx.x;
    const int n0 = (int)blockIdx.y * 64;

    // stage W once (first DIN cols of W_ih rows n0..n0+63)
    for (int i = t; i < 64 * 32; i += 128) {
        int row = i >> 5, c4 = i & 31;
        float4 v = *(const float4*)(W_ih + (size_t)(n0 + row) * KTOT + 4 * c4);
        __half2 h01 = __floats2half2_rn(v.x, v.y);
        __half2 h23 = __floats2half2_rn(v.z, v.w);
        *(uint2*)(sW + row * PCPAD + 4 * c4) =
            make_uint2(*(unsigned*)&h01, *(unsigned*)&h23);
    }

    const int wi = t >> 5, lane = t & 31;
    const int gg = lane >> 2, tg = lane & 3;
    const int mw = wi * 16;

    #pragma unroll 1
    for (int mt = 0; mt < 2; mt++) {
        const int m0 = (int)blockIdx.x * 128 + mt * 64;
        if (mt) __syncthreads();     // prior mma reads of sA done
        for (int i = t; i < 64 * 32; i += 128) {
            int row = i >> 5, c4 = i & 31;
            float4 v = *(const float4*)(inputs + (size_t)(m0 + row) * DIN + 4 * c4);
            __half2 h01 = __floats2half2_rn(v.x, v.y);
            __half2 h23 = __floats2half2_rn(v.z, v.w);
            *(uint2*)(sA + row * PCPAD + 4 * c4) =
                make_uint2(*(unsigned*)&h01, *(unsigned*)&h23);
        }
        __syncthreads();

        float d[8][4];
        #pragma unroll
        for (int nf = 0; nf < 8; nf++)
            #pragma unroll
            for (int c = 0; c < 4; c++) d[nf][c] = 0.f;

        #pragma unroll
        for (int ki = 0; ki < 8; ki++) {
            int k0 = 16 * ki;
            unsigned a0 = *(const unsigned*)(sA + (mw + gg)     * PCPAD + k0 + 2*tg);
            unsigned a1 = *(const unsigned*)(sA + (mw + 8 + gg) * PCPAD + k0 + 2*tg);
            unsigned a2 = *(const unsigned*)(sA + (mw + gg)     * PCPAD + k0 + 2*tg + 8);
            unsigned a3 = *(const unsigned*)(sA + (mw + 8 + gg) * PCPAD + k0 + 2*tg + 8);
            #pragma unroll
            for (int nf = 0; nf < 8; nf++) {
                unsigned b0 = *(const unsigned*)(sW + (8*nf + gg) * PCPAD + k0 + 2*tg);
                unsigned b1 = *(const unsigned*)(sW + (8*nf + gg) * PCPAD + k0 + 2*tg + 8);
                asm("mma.sync.aligned.m16n8k16.row.col.f32.f16.f16.f32 "
                    "{%0,%1,%2,%3}, {%4,%5,%6,%7}, {%8,%9}, {%0,%1,%2,%3};"
                    : "+f"(d[nf][0]), "+f"(d[nf][1]), "+f"(d[nf][2]), "+f"(d[nf][3])
                    : "r"(a0), "r"(a1), "r"(a2), "r"(a3), "r"(b0), "r"(b1));
            }
        }

        #pragma unroll
        for (int nf = 0; nf < 8; nf++) {
            __half2 lo = __floats2half2_rn(d[nf][0], d[nf][1]);
            __half2 hi = __floats2half2_rn(d[nf][2], d[nf][3]);
            size_t r0 = (size_t)(m0 + mw + gg)     * Hh + n0 + 8*nf + 2*tg;
            size_t r1 = (size_t)(m0 + mw + 8 + gg) * Hh + n0 + 8*nf + 2*tg;
            *(unsigned*)&g_U[r0] = *(unsigned*)&lo;
            *(unsigned*)&g_U[r1] = *(unsigned*)&hi;
        }
    }
}

// ============================================================================
// Persistent recurrence on TENSOR CORES: 128 CTAs x 256 threads (8 warps).
// Per step: h_new[2,256] = lrelu(A[16,256] @ B[256,256] + U + b), A rows 2..15
// are hard zeros living only in fragment registers. W_hh = B-fragments, fully
// register-resident (128 regs/thread). 1 barrier/step, h state fp16 in smem.
// ============================================================================
#define SH_PAD 264   // halves per state row (bank stagger)

__global__ void __launch_bounds__(256, 1)
rnn_persist_kernel(const float* __restrict__ h0,       // [B, H]
                   const float* __restrict__ W_ih,     // [H, KTOT]
                   const float* __restrict__ b_ih,     // [H]
                   float* __restrict__ out_h)          // [B, T+1, H]
{
    __shared__ __half shH[2][2][SH_PAD];   // [buf][row][col]

    const int t    = threadIdx.x;
    const int wi   = t >> 5;               // warp: n-cols [wi*32, wi*32+32)
    const int lane = t & 31;
    const bool active = (lane < 8);        // lanes holding rows 0,1 of A/D frags
    const int r    = (lane >> 2) & 1;      // batch row within CTA (valid if active)
    const int tg   = lane & 3;
    const int row0 = (int)blockIdx.x * 2;

    // ---- 1) W_hh as register-resident B fragments: b[nt][kt][2] ----
    // B[k][n] = W_ih[n][DIN+k]; frag: b0 = {B[2tg,n],B[2tg+1,n]}, b1 = k+8,
    // n = nt*8 + (lane>>2).
    unsigned bfr[4][16][2];
    #pragma unroll
    for (int nt = 0; nt < 4; nt++) {
        const int n = wi * 32 + nt * 8 + (lane >> 2);
        const float* wr = W_ih + (size_t)n * KTOT + DIN;
        #pragma unroll
        for (int kt = 0; kt < 16; kt++) {
            float2 f0 = __ldg((const float2*)(wr + kt * 16 + 2 * tg));
            float2 f1 = __ldg((const float2*)(wr + kt * 16 + 2 * tg + 8));
            __half2 h0v = __floats2half2_rn(f0.x, f0.y);
            __half2 h1v = __floats2half2_rn(f1.x, f1.y);
            bfr[nt][kt][0] = *(unsigned*)&h0v;
            bfr[nt][kt][1] = *(unsigned*)&h1v;
        }
    }

    // ---- 2) init state buffer 0 = fp16(h0); t=0 fp32 outputs ----
    for (int i = t; i < 2 * Hh; i += 256) {
        int rr = i >> 8, c = i & 255;
        float v = h0[(size_t)(row0 + rr) * Hh + c];
        shH[0][rr][c] = __float2half_rn(v);
        out_h[(size_t)(row0 + rr) * (Tt + 1) * Hh + c] = v;
    }

    // ---- 3) per-lane epilogue constants (active lanes only) ----
    int coff[4];
    float2 bi[4];
    #pragma unroll
    for (int nt = 0; nt < 4; nt++) {
        coff[nt] = wi * 32 + nt * 8 + 2 * tg;
        bi[nt] = active ? __ldg((const float2*)(b_ih + coff[nt]))
                        : make_float2(0.f, 0.f);
    }
    const __half* Ub = g_U + (size_t)(row0 + r) * Tt * Hh;
    float* hx = out_h + (size_t)(row0 + r) * (Tt + 1) * Hh;

    unsigned cU[4] = {0, 0, 0, 0};
    if (active) {
        #pragma unroll
        for (int nt = 0; nt < 4; nt++)
            cU[nt] = *(const unsigned*)(Ub + coff[nt]);
    }

    const unsigned zero = 0;
    __syncthreads();

    #pragma unroll 1
    for (int step = 0; step < Tt; step++) {
        const int p = step & 1;

        // prefetch next-step U (latency hidden by the mma block)
        unsigned nU[4] = {0, 0, 0, 0};
        if (active && step + 1 < Tt) {
            #pragma unroll
            for (int nt = 0; nt < 4; nt++)
                nU[nt] = *(const unsigned*)(Ub + (size_t)(step + 1) * Hh + coff[nt]);
        }

        float d[4][4];
        #pragma unroll
        for (int nt = 0; nt < 4; nt++)
            #pragma unroll
            for (int c = 0; c < 4; c++) d[nt][c] = 0.f;

        // ---- mma: 16 k-tiles x 4 n-tiles ----
        #pragma unroll
        for (int kt = 0; kt < 16; kt++) {
            unsigned a0 = 0, a2 = 0;
            if (active) {
                a0 = *(const unsigned*)&shH[p][r][kt * 16 + 2 * tg];
                a2 = *(const unsigned*)&shH[p][r][kt * 16 + 2 * tg + 8];
            }
            #pragma unroll
            for (int nt = 0; nt < 4; nt++) {
                asm("mma.sync.aligned.m16n8k16.row.col.f32.f16.f16.f32 "
                    "{%0,%1,%2,%3}, {%4,%5,%6,%7}, {%8,%9}, {%0,%1,%2,%3};"
                    : "+f"(d[nt][0]), "+f"(d[nt][1]), "+f"(d[nt][2]), "+f"(d[nt][3])
                    : "r"(a0), "r"(zero), "r"(a2), "r"(zero),
                      "r"(bfr[nt][kt][0]), "r"(bfr[nt][kt][1]));
            }
        }

        // ---- epilogue: d.c0/c1 = pre(row r, cols coff[nt], coff[nt]+1) ----
        if (active) {
            #pragma unroll
            for (int nt = 0; nt < 4; nt++) {
                float2 u = __half22float2(*(const __half2*)&cU[nt]);
                float xv = lrelu(d[nt][0] + u.x + bi[nt].x);
                float yv = lrelu(d[nt][1] + u.y + bi[nt].y);
                __half2 hh = __floats2half2_rn(xv, yv);
                *(unsigned*)&shH[p ^ 1][r][coff[nt]] = *(unsigned*)&hh;
                *(float2*)(hx + (size_t)(step + 1) * Hh + coff[nt]) =
                    make_float2(xv, yv);
            }
        }
        #pragma unroll
        for (int nt = 0; nt < 4; nt++) cU[nt] = nU[nt];

        __syncthreads();   // single barrier per step
    }
}

// ============================================================================
// Output projection (fully parallel, fp32 FFMA2 — unchanged, validated)
// ============================================================================
#define G2_ROWS 32
#define G2_SMEM (64*64*16 + G2_ROWS*Hh*4)   // 98304

__global__ void __launch_bounds__(256, 2)
gemm2_kernel(const float* __restrict__ out_h,
             const float* __restrict__ W_ho,
             const float* __restrict__ b_ho,
             float* __restrict__ out_x)
{
    extern __shared__ float smem[];
    float* sw = smem;            // [64 j4][64 d] float4 view
    float* sh = smem + 16384;    // [32 rows][256]

    const int t   = threadIdx.x;
    const int b   = blockIdx.y;
    const int tt0 = 1 + (int)blockIdx.x * 128;

    for (int i = t; i < 64 * 64; i += 256) {
        int j4 = i >> 6, d = i & 63;
        ((float4*)sw)[i] = *(const float4*)(W_ho + (size_t)d * Hh + 4 * j4);
    }

    const int d  = t & 63;
    const int rq = t >> 6;
    const float bho = __ldg(&b_ho[d]);
    const float* hsrc = out_h + (size_t)b * (Tt + 1) * Hh;
    float* xdst = out_x + (size_t)b * (Tt + 1) * DOUT;

    #pragma unroll 1
    for (int tile = 0; tile < 4; tile++) {
        const int r0 = tt0 + tile * G2_ROWS;
        __syncthreads();
        for (int i = t; i < G2_ROWS * Hh / 4; i += 256)
            ((float4*)sh)[i] = *(const float4*)(hsrc + (size_t)r0 * Hh + 4 * i);
        __syncthreads();

        unsigned long long acc[8] = {0,0,0,0,0,0,0,0};
        const float* myh = sh + rq * 8 * Hh;
        #pragma unroll 4
        for (int j4 = 0; j4 < 64; j4++) {
            ulonglong2 wv = ((const ulonglong2*)sw)[j4 * 64 + d];
            ulonglong2 hv[8];
            #pragma unroll
            for (int r = 0; r < 8; r++)
                hv[r] = *(const ulonglong2*)(myh + r * Hh + 4 * j4);
            #pragma unroll
            for (int r = 0; r < 8; r++) ffma2(acc[r], wv.x, hv[r].x);
            #pragma unroll
            for (int r = 0; r < 8; r++) ffma2(acc[r], wv.y, hv[r].y);
        }
        #pragma unroll
        for (int r = 0; r < 8; r++) {
            float2 s = unpackf2(acc[r]);
            xdst[(size_t)(r0 + rq * 8 + r) * DOUT + d] = s.x + s.y + bho;
        }
    }
}

__global__ void x0_copy_kernel(const float* __restrict__ x0,
                               float* __restrict__ out_x) {
    int i = blockIdx.x * blockDim.x + threadIdx.x;
    if (i < Bb * DOUT) {
        int b = i / DOUT, d = i % DOUT;
        out_x[(size_t)b * (Tt + 1) * DOUT + d] = x0[i];
    }
}

// Keep the persistent kernel at launch index 3 mod 6 (ncu capture slot).
__global__ void nop_a_kernel() {}
__global__ void nop_b_kernel() {}

extern "C" void kernel_launch(void* const* d_in, const int* in_sizes, int n_in,
                              void* d_out, int out_size) {
    const float* inputs = (const float*)d_in[0];
    const float* x0     = (const float*)d_in[1];
    const float* h0     = (const float*)d_in[2];
    const float* W_ih   = (const float*)d_in[3];
    const float* b_ih   = (const float*)d_in[4];
    const float* W_ho   = (const float*)d_in[5];
    const float* b_ho   = (const float*)d_in[6];

    float* out_x = (float*)d_out;                                  // [B, T+1, DOUT]
    float* out_h = out_x + (size_t)Bb * (Tt + 1) * DOUT;           // [B, T+1, H]

    cudaFuncSetAttribute(gemm2_kernel,
                         cudaFuncAttributeMaxDynamicSharedMemorySize,
                         (int)G2_SMEM);

    u_precompute_kernel<<<dim3(Bb * Tt / 128, Hh / 64), 128>>>(inputs, W_ih); // 0
    nop_a_kernel<<<1, 32>>>();                                                // 1
    nop_b_kernel<<<1, 32>>>();                                                // 2
    rnn_persist_kernel<<<Bb / 2, 256>>>(h0, W_ih, b_ih, out_h);               // 3
    gemm2_kernel<<<dim3(4, Bb), 256, G2_SMEM>>>(out_h, W_ho, b_ho, out_x);    // 4
    x0_copy_kernel<<<(Bb * DOUT + 255) / 256, 256>>>(x0, out_x);              // 5
}